// round 1
// baseline (speedup 1.0000x reference)
#include <cuda_runtime.h>
#include <math.h>

#define NT   16384   // total tokens
#define GN   128     // graphs
#define DD   128     // hidden dim
#define HN   4       // heads
#define DHD  32      // head dim
#define NBLK 10
#define MAXL 256
#define EPSV 1e-5f

// ---------------- scratch (device globals; no allocation allowed) ----------------
__device__ float g_x  [NT * DD];        // residual stream
__device__ float g_y  [NT * DD];        // LN output
__device__ float g_qkv[NT * 3 * DD];    // qkv
__device__ float g_att[NT * DD];        // attention output
__device__ float g_mlp[NT * 4 * DD];    // MLP hidden
__device__ float g_bn_mean[16];
__device__ float g_bn_rstd[16];
__device__ int   g_seg[GN + 1];

// ---------------- BN batch stats: one block per feature ----------------
__global__ void bn_stats_kernel(const float* __restrict__ s, const float* __restrict__ v) {
    int f = blockIdx.x;
    int t = threadIdx.x;
    float sum = 0.f, sq = 0.f;
    for (int i = t; i < NT; i += 256) {
        float x = (f < 13) ? s[i * 13 + f] : v[i * 3 + (f - 13)];
        sum += x; sq += x * x;
    }
    __shared__ float rs[256], rq[256];
    rs[t] = sum; rq[t] = sq;
    __syncthreads();
    for (int st = 128; st > 0; st >>= 1) {
        if (t < st) { rs[t] += rs[t + st]; rq[t] += rq[t + st]; }
        __syncthreads();
    }
    if (t == 0) {
        float m = rs[0] * (1.f / NT);
        float var = rq[0] * (1.f / NT) - m * m;
        g_bn_mean[f] = m;
        g_bn_rstd[f] = rsqrtf(var + EPSV);
    }
}

// ---------------- segment offsets via binary search on sorted batch_idx ----------------
__global__ void seg_kernel(const int* __restrict__ bidx) {
    int g = threadIdx.x;
    if (g > GN) return;
    int lo = 0, hi = NT;
    while (lo < hi) {
        int mid = (lo + hi) >> 1;
        if (bidx[mid] < g) lo = mid + 1; else hi = mid;
    }
    g_seg[g] = lo;
}

// ---------------- fused BN + input embedding (16 -> 128) ----------------
__global__ void embed_kernel(const float* __restrict__ s, const float* __restrict__ v,
                             const float* __restrict__ gamma, const float* __restrict__ beta,
                             const float* __restrict__ w_in, const float* __restrict__ b_in) {
    int row = blockIdx.x;
    int t = threadIdx.x;  // 128
    __shared__ float xn[16];
    if (t < 16) {
        float x = (t < 13) ? s[row * 13 + t] : v[row * 3 + (t - 13)];
        xn[t] = (x - g_bn_mean[t]) * g_bn_rstd[t] * gamma[t] + beta[t];
    }
    __syncthreads();
    float acc = b_in[t];
#pragma unroll
    for (int k = 0; k < 16; k++) acc += xn[k] * w_in[k * DD + t];
    g_x[row * DD + t] = acc;
}

// ---------------- LayerNorm: g_x -> g_y, one block (128 thr) per row ----------------
__global__ void ln_kernel(const float* __restrict__ gam, const float* __restrict__ bet) {
    int row = blockIdx.x;
    int t = threadIdx.x;
    float x = g_x[row * DD + t];
    float s = x, sq = x * x;
#pragma unroll
    for (int o = 16; o; o >>= 1) {
        s  += __shfl_xor_sync(0xffffffffu, s,  o);
        sq += __shfl_xor_sync(0xffffffffu, sq, o);
    }
    __shared__ float ws[4], wq[4];
    int w = t >> 5, l = t & 31;
    if (l == 0) { ws[w] = s; wq[w] = sq; }
    __syncthreads();
    s  = ws[0] + ws[1] + ws[2] + ws[3];
    sq = wq[0] + wq[1] + wq[2] + wq[3];
    float m = s * (1.f / DD);
    float var = sq * (1.f / DD) - m * m;
    float r = rsqrtf(var + EPSV);
    g_y[row * DD + t] = (x - m) * r * gam[t] + bet[t];
}

// ---------------- tiled SGEMM: C[M,Nc] = A[M,K] @ B[K,Nc] + bias (+res)(+gelu) ----------------
// BM=128, BN=128, BK=8, 256 threads, 8x8 per thread. M=NT, Nc % 128 == 0, K % 8 == 0.
// FUSE: 0 = bias only, 1 = bias + residual, 2 = bias + gelu
template <int FUSE>
__global__ __launch_bounds__(256)
void gemm_kernel(const float* __restrict__ A, const float* __restrict__ B,
                 const float* __restrict__ bias, const float* __restrict__ R,
                 float* __restrict__ C, int K, int Nc) {
    __shared__ float As[8][128];
    __shared__ float Bs[8][128];
    int bn = blockIdx.x, bm = blockIdx.y;
    int tid = threadIdx.x;
    int tx = tid & 15, ty = tid >> 4;

    const float* Ablk = A + (size_t)bm * 128 * K;
    const float* Bblk = B + bn * 128;

    int arow = tid >> 1;
    int acol = (tid & 1) * 4;
    int brow = tid >> 5;
    int bcol = (tid & 31) * 4;

    float acc[8][8];
#pragma unroll
    for (int i = 0; i < 8; i++)
#pragma unroll
        for (int j = 0; j < 8; j++) acc[i][j] = 0.f;

    for (int k0 = 0; k0 < K; k0 += 8) {
        float4 a4 = *(const float4*)(Ablk + (size_t)arow * K + k0 + acol);
        As[acol + 0][arow] = a4.x;
        As[acol + 1][arow] = a4.y;
        As[acol + 2][arow] = a4.z;
        As[acol + 3][arow] = a4.w;
        float4 b4 = *(const float4*)(Bblk + (size_t)(k0 + brow) * Nc + bcol);
        *(float4*)&Bs[brow][bcol] = b4;
        __syncthreads();
#pragma unroll
        for (int k = 0; k < 8; k++) {
            float a[8], b[8];
            *(float4*)(a)     = *(float4*)&As[k][ty * 8];
            *(float4*)(a + 4) = *(float4*)&As[k][ty * 8 + 4];
            *(float4*)(b)     = *(float4*)&Bs[k][tx * 8];
            *(float4*)(b + 4) = *(float4*)&Bs[k][tx * 8 + 4];
#pragma unroll
            for (int i = 0; i < 8; i++)
#pragma unroll
                for (int j = 0; j < 8; j++) acc[i][j] += a[i] * b[j];
        }
        __syncthreads();
    }

#pragma unroll
    for (int i = 0; i < 8; i++) {
        int row = bm * 128 + ty * 8 + i;
        float* crow = C + (size_t)row * Nc + bn * 128;
        const float* rrow = (FUSE == 1) ? (R + (size_t)row * Nc + bn * 128) : nullptr;
#pragma unroll
        for (int j0 = 0; j0 < 8; j0 += 4) {
            int col = tx * 8 + j0;
            float cv[4];
#pragma unroll
            for (int j = 0; j < 4; j++) {
                float val = acc[i][j0 + j] + bias[bn * 128 + col + j];
                if (FUSE == 1) val += rrow[col + j];
                if (FUSE == 2) {
                    float u = val;
                    val = 0.5f * u * (1.0f + tanhf(0.7978845608028654f * (u + 0.044715f * u * u * u)));
                }
                cv[j] = val;
            }
            *(float4*)(crow + col) = *(float4*)cv;
        }
    }
}

// ---------------- segment attention: one CTA per (graph, head), online softmax ----------------
__global__ __launch_bounds__(128)
void attn_kernel() {
    extern __shared__ float sh[];  // sK[256*32] | sV[256*32]  -> 64 KB
    float* sK = sh;
    float* sV = sh + MAXL * DHD;

    int g = blockIdx.x, h = blockIdx.y;
    int start = g_seg[g];
    int cnt = g_seg[g + 1] - start;
    if (cnt > MAXL) cnt = MAXL;  // safety (never hit with this data)
    int tid = threadIdx.x;

    // stage K and V for this head into smem
    for (int idx = tid; idx < cnt * DHD; idx += 128) {
        int j = idx >> 5, d = idx & 31;
        const float* base = g_qkv + (size_t)(start + j) * (3 * DD) + h * DHD + d;
        sK[idx] = base[DD];       // k
        sV[idx] = base[2 * DD];   // v
    }
    __syncthreads();

    const float scale = 0.17677669529663687f;  // 1/sqrt(32)

    for (int i = tid; i < cnt; i += 128) {
        float q[32];
        const float* qp = g_qkv + (size_t)(start + i) * (3 * DD) + h * DHD;
#pragma unroll
        for (int d4 = 0; d4 < 8; d4++) {
            float4 qq = *(const float4*)(qp + d4 * 4);
            q[d4 * 4 + 0] = qq.x * scale;
            q[d4 * 4 + 1] = qq.y * scale;
            q[d4 * 4 + 2] = qq.z * scale;
            q[d4 * 4 + 3] = qq.w * scale;
        }
        float m = -1e30f, l = 0.f;
        float acc[32];
#pragma unroll
        for (int d = 0; d < 32; d++) acc[d] = 0.f;

        for (int j = 0; j < cnt; j++) {
            float s = 0.f;
            const float* kr = sK + j * DHD;
#pragma unroll
            for (int d4 = 0; d4 < 8; d4++) {
                float4 kk = *(const float4*)(kr + d4 * 4);
                s += q[d4 * 4 + 0] * kk.x + q[d4 * 4 + 1] * kk.y
                   + q[d4 * 4 + 2] * kk.z + q[d4 * 4 + 3] * kk.w;
            }
            float mn = fmaxf(m, s);
            float corr = __expf(m - mn);
            float p = __expf(s - mn);
            l = l * corr + p;
            const float* vr = sV + j * DHD;
#pragma unroll
            for (int d4 = 0; d4 < 8; d4++) {
                float4 vv = *(const float4*)(vr + d4 * 4);
                acc[d4 * 4 + 0] = acc[d4 * 4 + 0] * corr + p * vv.x;
                acc[d4 * 4 + 1] = acc[d4 * 4 + 1] * corr + p * vv.y;
                acc[d4 * 4 + 2] = acc[d4 * 4 + 2] * corr + p * vv.z;
                acc[d4 * 4 + 3] = acc[d4 * 4 + 3] * corr + p * vv.w;
            }
            m = mn;
        }
        float inv = 1.f / l;
        float* op = g_att + (size_t)(start + i) * DD + h * DHD;
#pragma unroll
        for (int d4 = 0; d4 < 8; d4++) {
            float4 ov;
            ov.x = acc[d4 * 4 + 0] * inv;
            ov.y = acc[d4 * 4 + 1] * inv;
            ov.z = acc[d4 * 4 + 2] * inv;
            ov.w = acc[d4 * 4 + 3] * inv;
            *(float4*)(op + d4 * 4) = ov;
        }
    }
}

// ---------------- final projection 128 -> 4 (+ sigmoid on col 3) ----------------
__global__ void out_kernel(const float* __restrict__ w_out, const float* __restrict__ b_out,
                           float* __restrict__ out) {
    int row = blockIdx.x;
    int t = threadIdx.x;  // 128
    float x = g_y[row * DD + t];
    float p0 = x * w_out[t * 4 + 0];
    float p1 = x * w_out[t * 4 + 1];
    float p2 = x * w_out[t * 4 + 2];
    float p3 = x * w_out[t * 4 + 3];
#pragma unroll
    for (int o = 16; o; o >>= 1) {
        p0 += __shfl_xor_sync(0xffffffffu, p0, o);
        p1 += __shfl_xor_sync(0xffffffffu, p1, o);
        p2 += __shfl_xor_sync(0xffffffffu, p2, o);
        p3 += __shfl_xor_sync(0xffffffffu, p3, o);
    }
    __shared__ float s4[4][4];
    int w = t >> 5, l = t & 31;
    if (l == 0) { s4[w][0] = p0; s4[w][1] = p1; s4[w][2] = p2; s4[w][3] = p3; }
    __syncthreads();
    if (t < 4) {
        float v = s4[0][t] + s4[1][t] + s4[2][t] + s4[3][t] + b_out[t];
        if (t == 3) v = 1.f / (1.f + __expf(-v));
        out[row * 4 + t] = v;
    }
}

// ---------------- launcher ----------------
extern "C" void kernel_launch(void* const* d_in, const int* in_sizes, int n_in,
                              void* d_out, int out_size) {
    const float* inputs_scalar = (const float*)d_in[0];
    const float* inputs_v      = (const float*)d_in[1];
    const int*   batch_idx     = (const int*)  d_in[2];
    const float* bn_gamma      = (const float*)d_in[3];
    const float* bn_beta       = (const float*)d_in[4];
    const float* w_in          = (const float*)d_in[5];
    const float* b_in          = (const float*)d_in[6];
    const float* ln1_g         = (const float*)d_in[7];
    const float* ln1_b         = (const float*)d_in[8];
    const float* w_qkv         = (const float*)d_in[9];
    const float* b_qkv         = (const float*)d_in[10];
    const float* w_o           = (const float*)d_in[11];
    const float* b_o           = (const float*)d_in[12];
    const float* ln2_g         = (const float*)d_in[13];
    const float* ln2_b         = (const float*)d_in[14];
    const float* w_m1          = (const float*)d_in[15];
    const float* b_m1          = (const float*)d_in[16];
    const float* w_m2          = (const float*)d_in[17];
    const float* b_m2          = (const float*)d_in[18];
    const float* lnf_g         = (const float*)d_in[19];
    const float* lnf_b         = (const float*)d_in[20];
    const float* w_out         = (const float*)d_in[21];
    const float* b_out         = (const float*)d_in[22];
    float* out = (float*)d_out;

    (void)in_sizes; (void)n_in; (void)out_size;

    // 64 KB dynamic smem for attention K/V staging (idempotent, host-side; not a stream op)
    cudaFuncSetAttribute(attn_kernel, cudaFuncAttributeMaxDynamicSharedMemorySize, 65536);

    float *px, *py, *pq, *pa, *pm;
    cudaGetSymbolAddress((void**)&px, g_x);
    cudaGetSymbolAddress((void**)&py, g_y);
    cudaGetSymbolAddress((void**)&pq, g_qkv);
    cudaGetSymbolAddress((void**)&pa, g_att);
    cudaGetSymbolAddress((void**)&pm, g_mlp);

    bn_stats_kernel<<<16, 256>>>(inputs_scalar, inputs_v);
    seg_kernel<<<1, 256>>>(batch_idx);
    embed_kernel<<<NT, 128>>>(inputs_scalar, inputs_v, bn_gamma, bn_beta, w_in, b_in);

    for (int i = 0; i < NBLK; i++) {
        ln_kernel<<<NT, 128>>>(ln1_g + i * DD, ln1_b + i * DD);
        gemm_kernel<0><<<dim3(3, NT / 128), 256>>>(
            py, w_qkv + (size_t)i * DD * 3 * DD, b_qkv + i * 3 * DD, nullptr, pq, DD, 3 * DD);
        attn_kernel<<<dim3(GN, HN), 128, 65536>>>();
        gemm_kernel<1><<<dim3(1, NT / 128), 256>>>(
            pa, w_o + (size_t)i * DD * DD, b_o + i * DD, px, px, DD, DD);
        ln_kernel<<<NT, 128>>>(ln2_g + i * DD, ln2_b + i * DD);
        gemm_kernel<2><<<dim3(4, NT / 128), 256>>>(
            py, w_m1 + (size_t)i * DD * 4 * DD, b_m1 + i * 4 * DD, nullptr, pm, DD, 4 * DD);
        gemm_kernel<1><<<dim3(1, NT / 128), 256>>>(
            pm, w_m2 + (size_t)i * 4 * DD * DD, b_m2 + i * DD, px, px, 4 * DD, DD);
    }

    ln_kernel<<<NT, 128>>>(lnf_g, lnf_b);
    out_kernel<<<NT, 128>>>(w_out, b_out, out);
}

// round 3
// speedup vs baseline: 1.5622x; 1.5622x over previous
#include <cuda_runtime.h>
#include <cuda_bf16.h>
#include <cstdint>
#include <math.h>

#define NT   16384
#define GN   128
#define DD   128
#define HN   4
#define DHD  32
#define NBLK 10
#define MAXL 256
#define EPSV 1e-5f

typedef __nv_bfloat16 bf16;

// ---------------- scratch ----------------
__device__ float g_x  [NT * DD];          // residual stream (fp32)
__device__ float g_qkv[NT * 3 * DD];      // qkv (fp32)
__device__ bf16  g_yh [NT * DD];          // LN output hi/lo
__device__ bf16  g_yl [NT * DD];
__device__ bf16  g_ah [NT * DD];          // attention output hi/lo
__device__ bf16  g_al [NT * DD];
__device__ bf16  g_mh [NT * 4 * DD];      // MLP hidden hi/lo
__device__ bf16  g_ml [NT * 4 * DD];
__device__ float g_bn_mean[16];
__device__ float g_bn_rstd[16];
__device__ int   g_seg[GN + 1];

// bf16 hi/lo weights, transposed to [N][K]
__device__ bf16 g_wq_hi [NBLK * 384 * 128];
__device__ bf16 g_wq_lo [NBLK * 384 * 128];
__device__ bf16 g_wo_hi [NBLK * 128 * 128];
__device__ bf16 g_wo_lo [NBLK * 128 * 128];
__device__ bf16 g_wm1_hi[NBLK * 512 * 128];
__device__ bf16 g_wm1_lo[NBLK * 512 * 128];
__device__ bf16 g_wm2_hi[NBLK * 128 * 512];
__device__ bf16 g_wm2_lo[NBLK * 128 * 512];

// ---------------- asm helpers ----------------
__device__ __forceinline__ uint32_t smem_u32(const void* p) {
    uint32_t a;
    asm("{ .reg .u64 t; cvta.to.shared.u64 t, %1; cvt.u32.u64 %0, t; }" : "=r"(a) : "l"(p));
    return a;
}
__device__ __forceinline__ void cp16(uint32_t dst, const void* src) {
    asm volatile("cp.async.cg.shared.global [%0], [%1], 16;" :: "r"(dst), "l"(src));
}
#define CP_COMMIT() asm volatile("cp.async.commit_group;" ::: "memory")
#define CP_WAIT(n)  asm volatile("cp.async.wait_group %0;" :: "n"(n) : "memory")

__device__ __forceinline__ void ldm_x4(uint32_t r[4], uint32_t a) {
    asm volatile("ldmatrix.sync.aligned.m8n8.x4.shared.b16 {%0,%1,%2,%3}, [%4];"
                 : "=r"(r[0]), "=r"(r[1]), "=r"(r[2]), "=r"(r[3]) : "r"(a));
}
__device__ __forceinline__ void mma_bf16(float c[4], const uint32_t a[4],
                                         uint32_t b0, uint32_t b1) {
    asm volatile(
        "mma.sync.aligned.m16n8k16.row.col.f32.bf16.bf16.f32 "
        "{%0,%1,%2,%3}, {%4,%5,%6,%7}, {%8,%9}, {%0,%1,%2,%3};"
        : "+f"(c[0]), "+f"(c[1]), "+f"(c[2]), "+f"(c[3])
        : "r"(a[0]), "r"(a[1]), "r"(a[2]), "r"(a[3]), "r"(b0), "r"(b1));
}

__device__ __forceinline__ void split_bf16(float v, bf16& hi, bf16& lo) {
    hi = __float2bfloat16(v);
    lo = __float2bfloat16(v - __bfloat162float(hi));
}
__device__ __forceinline__ float fast_gelu(float u) {
    float z = 0.7978845608028654f * (u + 0.044715f * u * u * u);
    float t = 1.f - 2.f / (__expf(2.f * z) + 1.f);   // tanh(z)
    return 0.5f * u * (1.f + t);
}

// ---------------- BN batch stats ----------------
__global__ void bn_stats_kernel(const float* __restrict__ s, const float* __restrict__ v) {
    int f = blockIdx.x, t = threadIdx.x;
    float sum = 0.f, sq = 0.f;
    for (int i = t; i < NT; i += 256) {
        float x = (f < 13) ? s[i * 13 + f] : v[i * 3 + (f - 13)];
        sum += x; sq += x * x;
    }
    __shared__ float rs[256], rq[256];
    rs[t] = sum; rq[t] = sq;
    __syncthreads();
    for (int st = 128; st > 0; st >>= 1) {
        if (t < st) { rs[t] += rs[t + st]; rq[t] += rq[t + st]; }
        __syncthreads();
    }
    if (t == 0) {
        float m = rs[0] * (1.f / NT);
        float var = rq[0] * (1.f / NT) - m * m;
        g_bn_mean[f] = m;
        g_bn_rstd[f] = rsqrtf(var + EPSV);
    }
}

// ---------------- segment offsets ----------------
__global__ void seg_kernel(const int* __restrict__ bidx) {
    int g = threadIdx.x;
    if (g > GN) return;
    int lo = 0, hi = NT;
    while (lo < hi) {
        int mid = (lo + hi) >> 1;
        if (bidx[mid] < g) lo = mid + 1; else hi = mid;
    }
    g_seg[g] = lo;
}

// ---------------- BN + embed ----------------
__global__ void embed_kernel(const float* __restrict__ s, const float* __restrict__ v,
                             const float* __restrict__ gamma, const float* __restrict__ beta,
                             const float* __restrict__ w_in, const float* __restrict__ b_in) {
    int row = blockIdx.x, t = threadIdx.x;
    __shared__ float xn[16];
    if (t < 16) {
        float x = (t < 13) ? s[row * 13 + t] : v[row * 3 + (t - 13)];
        xn[t] = (x - g_bn_mean[t]) * g_bn_rstd[t] * gamma[t] + beta[t];
    }
    __syncthreads();
    float acc = b_in[t];
#pragma unroll
    for (int k = 0; k < 16; k++) acc += xn[k] * w_in[k * DD + t];
    g_x[row * DD + t] = acc;
}

// ---------------- LayerNorm: warp per row -> hi/lo bf16 ----------------
__global__ __launch_bounds__(256)
void ln_kernel(const float* __restrict__ gam, const float* __restrict__ bet) {
    int w = threadIdx.x >> 5, lane = threadIdx.x & 31;
    int row = blockIdx.x * 8 + w;
    const float* xp = g_x + (size_t)row * DD;
    float4 xv = *(const float4*)(xp + lane * 4);
    float s = xv.x + xv.y + xv.z + xv.w;
    float sq = xv.x * xv.x + xv.y * xv.y + xv.z * xv.z + xv.w * xv.w;
#pragma unroll
    for (int o = 16; o; o >>= 1) {
        s  += __shfl_xor_sync(0xffffffffu, s,  o);
        sq += __shfl_xor_sync(0xffffffffu, sq, o);
    }
    float m = s * (1.f / DD);
    float var = sq * (1.f / DD) - m * m;
    float r = rsqrtf(var + EPSV);
    float4 gv = *(const float4*)(gam + lane * 4);
    float4 bv = *(const float4*)(bet + lane * 4);
    float o0 = (xv.x - m) * r * gv.x + bv.x;
    float o1 = (xv.y - m) * r * gv.y + bv.y;
    float o2 = (xv.z - m) * r * gv.z + bv.z;
    float o3 = (xv.w - m) * r * gv.w + bv.w;
    bf16 h[4], l[4];
    split_bf16(o0, h[0], l[0]); split_bf16(o1, h[1], l[1]);
    split_bf16(o2, h[2], l[2]); split_bf16(o3, h[3], l[3]);
    *(uint2*)(g_yh + (size_t)row * DD + lane * 4) = *(uint2*)h;
    *(uint2*)(g_yl + (size_t)row * DD + lane * 4) = *(uint2*)l;
}

// ---------------- weight prep: [NB,K,N] fp32 -> [NB,N,K] bf16 hi/lo ----------------
__global__ void wprep_kernel(const float* __restrict__ w, bf16* __restrict__ whi,
                             bf16* __restrict__ wlo, int K, int N) {
    int idx = blockIdx.x * 256 + threadIdx.x;
    int total = NBLK * N * K;
    if (idx >= total) return;
    int k = idx % K;
    int n = (idx / K) % N;
    int b = idx / (K * N);
    float x = w[(size_t)b * K * N + (size_t)k * N + n];
    bf16 hi, lo;
    split_bf16(x, hi, lo);
    whi[idx] = hi;
    wlo[idx] = lo;
}

// ---------------- mma.sync GEMM: C[M,Nc] = A @ W^T, bf16 hi/lo compensated ----------------
// CTA 128x128, BK=16, 8 warps (32x64 each), 2-stage cp.async pipeline.
// A: [M][K] bf16 hi/lo. B: [Nc][K] bf16 hi/lo.
// FUSE: 0 bias->fp32, 1 bias+residual->fp32, 2 bias+gelu->hi/lo bf16
#define STG 24576            // bytes per pipeline stage
#define OFF_AH 0
#define OFF_AL 6144
#define OFF_BH 12288
#define OFF_BL 18432
#define GEMM_SMEM (2 * STG)  // 48 KB

template <int FUSE>
__global__ __launch_bounds__(256)
void gemm_mma(const bf16* __restrict__ Ahi, const bf16* __restrict__ Alo,
              const bf16* __restrict__ Bhi, const bf16* __restrict__ Blo,
              const float* __restrict__ bias, const float* __restrict__ R,
              float* __restrict__ C, bf16* __restrict__ Chi, bf16* __restrict__ Clo,
              int K, int Nc) {
    extern __shared__ char smem[];
    uint32_t sb = smem_u32(smem);
    int tid = threadIdx.x, lane = tid & 31, wid = tid >> 5;
    int wm = wid & 3, wn = wid >> 2;             // warp tile: rows wm*32, cols wn*64
    int m0 = blockIdx.y * 128, n0 = blockIdx.x * 128;

    int ldrow = tid >> 1, ldhalf = tid & 1;      // staging assignment
    const bf16* pAh = Ahi + (size_t)(m0 + ldrow) * K + ldhalf * 8;
    const bf16* pAl = Alo + (size_t)(m0 + ldrow) * K + ldhalf * 8;
    const bf16* pBh = Bhi + (size_t)(n0 + ldrow) * K + ldhalf * 8;
    const bf16* pBl = Blo + (size_t)(n0 + ldrow) * K + ldhalf * 8;
    uint32_t dstb = sb + ldrow * 48 + ldhalf * 16;

    float acc[2][8][4];
#pragma unroll
    for (int i = 0; i < 2; i++)
#pragma unroll
        for (int j = 0; j < 8; j++)
#pragma unroll
            for (int q = 0; q < 4; q++) acc[i][j][q] = 0.f;

    int nsteps = K >> 4;

    // prologue: stage 0
    {
        uint32_t d = dstb;
        cp16(d + OFF_AH, pAh);
        cp16(d + OFF_AL, pAl);
        cp16(d + OFF_BH, pBh);
        cp16(d + OFF_BL, pBl);
        CP_COMMIT();
    }

    // ldmatrix lane addresses (stage-relative)
    uint32_t a_off = (uint32_t)((wm * 32 + (lane & 15)) * 48 + (lane >> 4) * 16);
    uint32_t b_row = (uint32_t)(wn * 64 + (lane & 7) + ((lane >> 4) << 3));
    uint32_t b_off = b_row * 48 + (((lane >> 3) & 1) << 4);

    for (int c = 0; c < nsteps; c++) {
        if (c + 1 < nsteps) {
            int k0 = (c + 1) << 4;
            uint32_t d = dstb + ((c + 1) & 1) * STG;
            cp16(d + OFF_AH, pAh + k0);
            cp16(d + OFF_AL, pAl + k0);
            cp16(d + OFF_BH, pBh + k0);
            cp16(d + OFF_BL, pBl + k0);
            CP_COMMIT();
            CP_WAIT(1);
        } else {
            CP_WAIT(0);
        }
        __syncthreads();

        uint32_t sA = sb + (c & 1) * STG;
        uint32_t sB = sA + OFF_BH;

        uint32_t ah[2][4], al[2][4];
#pragma unroll
        for (int mt = 0; mt < 2; mt++) {
            uint32_t addr = sA + a_off + mt * 16 * 48;
            ldm_x4(ah[mt], addr + OFF_AH);
            ldm_x4(al[mt], addr + OFF_AL);
        }
        uint32_t bh[8][2], bl[8][2];
#pragma unroll
        for (int g4 = 0; g4 < 4; g4++) {
            uint32_t addr = sB + b_off + g4 * 16 * 48;
            uint32_t t4[4];
            ldm_x4(t4, addr);
            bh[g4 * 2][0] = t4[0]; bh[g4 * 2][1] = t4[1];
            bh[g4 * 2 + 1][0] = t4[2]; bh[g4 * 2 + 1][1] = t4[3];
            ldm_x4(t4, addr + (OFF_BL - OFF_BH));
            bl[g4 * 2][0] = t4[0]; bl[g4 * 2][1] = t4[1];
            bl[g4 * 2 + 1][0] = t4[2]; bl[g4 * 2 + 1][1] = t4[3];
        }
#pragma unroll
        for (int mt = 0; mt < 2; mt++)
#pragma unroll
            for (int nt = 0; nt < 8; nt++) {
                mma_bf16(acc[mt][nt], ah[mt], bh[nt][0], bh[nt][1]);
                mma_bf16(acc[mt][nt], ah[mt], bl[nt][0], bl[nt][1]);
                mma_bf16(acc[mt][nt], al[mt], bh[nt][0], bh[nt][1]);
            }
        __syncthreads();
    }

    // epilogue
    int lane4 = lane >> 2, lanem = (lane & 3) * 2;
#pragma unroll
    for (int mt = 0; mt < 2; mt++) {
#pragma unroll
        for (int nt = 0; nt < 8; nt++) {
            int col = n0 + wn * 64 + nt * 8 + lanem;
            int r0 = m0 + wm * 32 + mt * 16 + lane4;
            float b0 = bias[col], b1 = bias[col + 1];
#pragma unroll
            for (int half = 0; half < 2; half++) {
                int r = r0 + half * 8;
                float v0 = acc[mt][nt][half * 2 + 0] + b0;
                float v1 = acc[mt][nt][half * 2 + 1] + b1;
                size_t o = (size_t)r * Nc + col;
                if (FUSE == 1) {
                    float2 rr = *(const float2*)(R + o);
                    v0 += rr.x; v1 += rr.y;
                }
                if (FUSE == 2) {
                    v0 = fast_gelu(v0);
                    v1 = fast_gelu(v1);
                    bf16 h0, l0, h1, l1;
                    split_bf16(v0, h0, l0);
                    split_bf16(v1, h1, l1);
                    __nv_bfloat162 hh = {h0, h1}, ll = {l0, l1};
                    *(__nv_bfloat162*)(Chi + o) = hh;
                    *(__nv_bfloat162*)(Clo + o) = ll;
                } else {
                    float2 ov = {v0, v1};
                    *(float2*)(C + o) = ov;
                }
            }
        }
    }
}

// ---------------- segment attention (fp32), writes hi/lo ----------------
__global__ __launch_bounds__(128)
void attn_kernel() {
    extern __shared__ float sh[];
    float* sK = sh;
    float* sV = sh + MAXL * DHD;

    int g = blockIdx.x, h = blockIdx.y;
    int start = g_seg[g];
    int cnt = g_seg[g + 1] - start;
    if (cnt > MAXL) cnt = MAXL;
    int tid = threadIdx.x;

    for (int idx = tid; idx < cnt * DHD; idx += 128) {
        int j = idx >> 5, d = idx & 31;
        const float* base = g_qkv + (size_t)(start + j) * (3 * DD) + h * DHD + d;
        sK[idx] = base[DD];
        sV[idx] = base[2 * DD];
    }
    __syncthreads();

    const float scale = 0.17677669529663687f;

    for (int i = tid; i < cnt; i += 128) {
        float q[32];
        const float* qp = g_qkv + (size_t)(start + i) * (3 * DD) + h * DHD;
#pragma unroll
        for (int d4 = 0; d4 < 8; d4++) {
            float4 qq = *(const float4*)(qp + d4 * 4);
            q[d4 * 4 + 0] = qq.x * scale;
            q[d4 * 4 + 1] = qq.y * scale;
            q[d4 * 4 + 2] = qq.z * scale;
            q[d4 * 4 + 3] = qq.w * scale;
        }
        float m = -1e30f, l = 0.f;
        float acc[32];
#pragma unroll
        for (int d = 0; d < 32; d++) acc[d] = 0.f;

        for (int j = 0; j < cnt; j++) {
            float s = 0.f;
            const float* kr = sK + j * DHD;
#pragma unroll
            for (int d4 = 0; d4 < 8; d4++) {
                float4 kk = *(const float4*)(kr + d4 * 4);
                s += q[d4 * 4 + 0] * kk.x + q[d4 * 4 + 1] * kk.y
                   + q[d4 * 4 + 2] * kk.z + q[d4 * 4 + 3] * kk.w;
            }
            float mn = fmaxf(m, s);
            float corr = __expf(m - mn);
            float p = __expf(s - mn);
            l = l * corr + p;
            const float* vr = sV + j * DHD;
#pragma unroll
            for (int d4 = 0; d4 < 8; d4++) {
                float4 vv = *(const float4*)(vr + d4 * 4);
                acc[d4 * 4 + 0] = acc[d4 * 4 + 0] * corr + p * vv.x;
                acc[d4 * 4 + 1] = acc[d4 * 4 + 1] * corr + p * vv.y;
                acc[d4 * 4 + 2] = acc[d4 * 4 + 2] * corr + p * vv.z;
                acc[d4 * 4 + 3] = acc[d4 * 4 + 3] * corr + p * vv.w;
            }
            m = mn;
        }
        float inv = 1.f / l;
        bf16* oh = g_ah + (size_t)(start + i) * DD + h * DHD;
        bf16* ol = g_al + (size_t)(start + i) * DD + h * DHD;
#pragma unroll
        for (int d4 = 0; d4 < 8; d4++) {
            bf16 hh[4], ll[4];
#pragma unroll
            for (int q4 = 0; q4 < 4; q4++)
                split_bf16(acc[d4 * 4 + q4] * inv, hh[q4], ll[q4]);
            *(uint2*)(oh + d4 * 4) = *(uint2*)hh;
            *(uint2*)(ol + d4 * 4) = *(uint2*)ll;
        }
    }
}

// ---------------- final projection 128->4 ----------------
__global__ void out_kernel(const float* __restrict__ w_out, const float* __restrict__ b_out,
                           float* __restrict__ out) {
    int row = blockIdx.x;
    int t = threadIdx.x;
    float x = __bfloat162float(g_yh[(size_t)row * DD + t]) +
              __bfloat162float(g_yl[(size_t)row * DD + t]);
    float p0 = x * w_out[t * 4 + 0];
    float p1 = x * w_out[t * 4 + 1];
    float p2 = x * w_out[t * 4 + 2];
    float p3 = x * w_out[t * 4 + 3];
#pragma unroll
    for (int o = 16; o; o >>= 1) {
        p0 += __shfl_xor_sync(0xffffffffu, p0, o);
        p1 += __shfl_xor_sync(0xffffffffu, p1, o);
        p2 += __shfl_xor_sync(0xffffffffu, p2, o);
        p3 += __shfl_xor_sync(0xffffffffu, p3, o);
    }
    __shared__ float s4[4][4];
    int w = t >> 5, l = t & 31;
    if (l == 0) { s4[w][0] = p0; s4[w][1] = p1; s4[w][2] = p2; s4[w][3] = p3; }
    __syncthreads();
    if (t < 4) {
        float v = s4[0][t] + s4[1][t] + s4[2][t] + s4[3][t] + b_out[t];
        if (t == 3) v = 1.f / (1.f + __expf(-v));
        out[row * 4 + t] = v;
    }
}

// ---------------- launcher ----------------
extern "C" void kernel_launch(void* const* d_in, const int* in_sizes, int n_in,
                              void* d_out, int out_size) {
    const float* inputs_scalar = (const float*)d_in[0];
    const float* inputs_v      = (const float*)d_in[1];
    const int*   batch_idx     = (const int*)  d_in[2];
    const float* bn_gamma      = (const float*)d_in[3];
    const float* bn_beta       = (const float*)d_in[4];
    const float* w_in          = (const float*)d_in[5];
    const float* b_in          = (const float*)d_in[6];
    const float* ln1_g         = (const float*)d_in[7];
    const float* ln1_b         = (const float*)d_in[8];
    const float* w_qkv         = (const float*)d_in[9];
    const float* b_qkv         = (const float*)d_in[10];
    const float* w_o           = (const float*)d_in[11];
    const float* b_o           = (const float*)d_in[12];
    const float* ln2_g         = (const float*)d_in[13];
    const float* ln2_b         = (const float*)d_in[14];
    const float* w_m1          = (const float*)d_in[15];
    const float* b_m1          = (const float*)d_in[16];
    const float* w_m2          = (const float*)d_in[17];
    const float* b_m2          = (const float*)d_in[18];
    const float* lnf_g         = (const float*)d_in[19];
    const float* lnf_b         = (const float*)d_in[20];
    const float* w_out         = (const float*)d_in[21];
    const float* b_out         = (const float*)d_in[22];
    float* out = (float*)d_out;

    (void)in_sizes; (void)n_in; (void)out_size;

    cudaFuncSetAttribute(attn_kernel, cudaFuncAttributeMaxDynamicSharedMemorySize, 65536);
    cudaFuncSetAttribute(gemm_mma<0>, cudaFuncAttributeMaxDynamicSharedMemorySize, GEMM_SMEM);
    cudaFuncSetAttribute(gemm_mma<1>, cudaFuncAttributeMaxDynamicSharedMemorySize, GEMM_SMEM);
    cudaFuncSetAttribute(gemm_mma<2>, cudaFuncAttributeMaxDynamicSharedMemorySize, GEMM_SMEM);

    float *px, *pq;
    bf16 *yh, *yl, *ah, *al, *mh, *ml;
    cudaGetSymbolAddress((void**)&px, g_x);
    cudaGetSymbolAddress((void**)&pq, g_qkv);
    cudaGetSymbolAddress((void**)&yh, g_yh);
    cudaGetSymbolAddress((void**)&yl, g_yl);
    cudaGetSymbolAddress((void**)&ah, g_ah);
    cudaGetSymbolAddress((void**)&al, g_al);
    cudaGetSymbolAddress((void**)&mh, g_mh);
    cudaGetSymbolAddress((void**)&ml, g_ml);
    bf16 *wqh, *wql, *woh, *wol, *w1h, *w1l, *w2h, *w2l;
    cudaGetSymbolAddress((void**)&wqh, g_wq_hi);
    cudaGetSymbolAddress((void**)&wql, g_wq_lo);
    cudaGetSymbolAddress((void**)&woh, g_wo_hi);
    cudaGetSymbolAddress((void**)&wol, g_wo_lo);
    cudaGetSymbolAddress((void**)&w1h, g_wm1_hi);
    cudaGetSymbolAddress((void**)&w1l, g_wm1_lo);
    cudaGetSymbolAddress((void**)&w2h, g_wm2_hi);
    cudaGetSymbolAddress((void**)&w2l, g_wm2_lo);

    wprep_kernel<<<(NBLK * 384 * 128 + 255) / 256, 256>>>(w_qkv, wqh, wql, 128, 384);
    wprep_kernel<<<(NBLK * 128 * 128 + 255) / 256, 256>>>(w_o,   woh, wol, 128, 128);
    wprep_kernel<<<(NBLK * 512 * 128 + 255) / 256, 256>>>(w_m1,  w1h, w1l, 128, 512);
    wprep_kernel<<<(NBLK * 128 * 512 + 255) / 256, 256>>>(w_m2,  w2h, w2l, 512, 128);

    bn_stats_kernel<<<16, 256>>>(inputs_scalar, inputs_v);
    seg_kernel<<<1, 256>>>(batch_idx);
    embed_kernel<<<NT, 128>>>(inputs_scalar, inputs_v, bn_gamma, bn_beta, w_in, b_in);

    for (int i = 0; i < NBLK; i++) {
        ln_kernel<<<NT / 8, 256>>>(ln1_g + i * DD, ln1_b + i * DD);
        gemm_mma<0><<<dim3(3, NT / 128), 256, GEMM_SMEM>>>(
            yh, yl, wqh + (size_t)i * 384 * 128, wql + (size_t)i * 384 * 128,
            b_qkv + i * 3 * DD, nullptr, pq, nullptr, nullptr, 128, 384);
        attn_kernel<<<dim3(GN, HN), 128, 65536>>>();
        gemm_mma<1><<<dim3(1, NT / 128), 256, GEMM_SMEM>>>(
            ah, al, woh + (size_t)i * 128 * 128, wol + (size_t)i * 128 * 128,
            b_o + i * DD, px, px, nullptr, nullptr, 128, 128);
        ln_kernel<<<NT / 8, 256>>>(ln2_g + i * DD, ln2_b + i * DD);
        gemm_mma<2><<<dim3(4, NT / 128), 256, GEMM_SMEM>>>(
            yh, yl, w1h + (size_t)i * 512 * 128, w1l + (size_t)i * 512 * 128,
            b_m1 + i * 4 * DD, nullptr, nullptr, mh, ml, 128, 512);
        gemm_mma<1><<<dim3(1, NT / 128), 256, GEMM_SMEM>>>(
            mh, ml, w2h + (size_t)i * 128 * 512, w2l + (size_t)i * 128 * 512,
            b_m2 + i * DD, px, px, nullptr, nullptr, 512, 128);
    }

    ln_kernel<<<NT / 8, 256>>>(lnf_g, lnf_b);
    out_kernel<<<NT, 128>>>(w_out, b_out, out);
}